// round 3
// baseline (speedup 1.0000x reference)
#include <cuda_runtime.h>
#include <math.h>

// Problem constants
#define NN 4
#define C1 128
#define C2 36
#define Hh 192
#define Ww 192
#define HO 190
#define WO 190
#define HW (Hh*Ww)
#define HWO (HO*WO)
#define PB 128          // pixels per deform block
#define NT 288          // threads per deform block (9 warps)

// Scratch (device globals: allocation-free rule)
__device__ float g_offset[NN*C2*HO*WO];   // offset conv output [N,36,HO,WO]
__device__ float g_wt[9*C1*C2];           // deform_w transposed [tap][c][o], BN-scaled
__device__ float g_bias[C2];              // folded BN bias

// ---------------------------------------------------------------------------
// Prep: transpose deform_w [o][c][3][3] -> g_wt[tap][c][o], folding BN scale.
// ---------------------------------------------------------------------------
__global__ void prep_kernel(const float* __restrict__ dw,
                            const float* __restrict__ gamma,
                            const float* __restrict__ beta,
                            const float* __restrict__ mean,
                            const float* __restrict__ var)
{
    int idx = blockIdx.x * 256 + threadIdx.x;
    if (idx < 9 * C1 * C2) {
        int t = idx / (C1 * C2);
        int r = idx % (C1 * C2);
        int c = r / C2, o = r % C2;
        float s = gamma[o] * rsqrtf(var[o] + 1e-5f);
        g_wt[idx] = dw[(o * C1 + c) * 9 + t] * s;
    }
    if (idx < C2) {
        float s = gamma[idx] * rsqrtf(var[idx] + 1e-5f);
        g_bias[idx] = beta[idx] - mean[idx] * s;
    }
}

// ---------------------------------------------------------------------------
// Offset-generating grouped conv (groups=4, VALID, 3x3, stride 1)
// Round-1 known-good version: 32x6 pixel tile, one (n, group) per blockIdx.z.
// ---------------------------------------------------------------------------
__global__ __launch_bounds__(192) void offset_conv_kernel(
    const float* __restrict__ x, const float* __restrict__ cw)
{
    __shared__ float sx[32 * 8 * 34];   // 32 ch, 8 rows, 34 cols
    __shared__ float ws[32 * 9 * 9];    // [ci][tap][o]

    int n = blockIdx.z >> 2;
    int g = blockIdx.z & 3;
    int x0 = blockIdx.x * 32;
    int y0 = blockIdx.y * 6;
    int tid = threadIdx.x;

    for (int idx = tid; idx < 2592; idx += 192) {
        int o = idx % 9; int rem = idx / 9;
        int tap = rem % 9; int ci = rem / 9;
        ws[idx] = cw[((g * 9 + o) * 32 + ci) * 9 + tap];
    }

    const float* xb = x + ((size_t)n * C1 + g * 32) * HW;
    for (int idx = tid; idx < 32 * 8 * 34; idx += 192) {
        int ci = idx / 272;
        int r  = (idx % 272) / 34;
        int col = idx % 34;
        int gy = y0 + r, gx = x0 + col;
        float v = 0.f;
        if (gy < Hh && gx < Ww) v = xb[ci * HW + gy * Ww + gx];
        sx[idx] = v;
    }
    __syncthreads();

    int lx = tid & 31, ly = tid >> 5;
    float acc[9];
#pragma unroll
    for (int o = 0; o < 9; o++) acc[o] = 0.f;

    for (int ci = 0; ci < 32; ci++) {
        int base = ci * 272 + ly * 34 + lx;
#pragma unroll
        for (int tap = 0; tap < 9; tap++) {
            int i = tap / 3, j = tap % 3;
            float v = sx[base + i * 34 + j];
            const float* wp = &ws[(ci * 9 + tap) * 9];
#pragma unroll
            for (int o = 0; o < 9; o++) acc[o] = fmaf(v, wp[o], acc[o]);
        }
    }

    int yy = y0 + ly, xx = x0 + lx;
    if (yy < HO && xx < WO) {
        float* op = g_offset + ((size_t)n * C2 + g * 9) * HWO + yy * WO + xx;
#pragma unroll
        for (int o = 0; o < 9; o++) op[o * HWO] = acc[o];
    }
}

// ---------------------------------------------------------------------------
// Deformable conv + folded BN + Mish, block-GEMM formulation.
// Block = 128 pixels. Per (tap, dg):
//   - threads 0..255 bilinear-sample V[64c][128p] into smem
//   - all 288 threads: C[36o][128p] += W[c][o]^T V[c][p], 4x4 micro-tile
// ---------------------------------------------------------------------------
__global__ __launch_bounds__(NT, 3) void deform_kernel(
    const float* __restrict__ x, float* __restrict__ out)
{
    __shared__ float wts[64 * C2];     // current (tap,dg) weights [64c][36o] (9KB)
    __shared__ float vs[64 * PB];      // sampled values [64c][128p]      (32KB)

    int n = blockIdx.y;
    int p0 = blockIdx.x * PB;
    int tid = threadIdx.x;

    // GEMM micro-tile coords: o-block = to*4, p-block = tp*4
    int to = tid % 9;           // 0..8
    int tp = tid / 9;           // 0..31

    // sampling coords
    int sp  = tid & (PB - 1);           // pixel lane 0..127
    int sc0 = (tid >> 7) * 32;          // channel half: 0 or 32
    int pS  = min(p0 + sp, HWO - 1);
    int ysS = pS / WO, xsS = pS % WO;

    const float* xb = x + (size_t)n * C1 * HW;
    const float* offbase = g_offset + (size_t)n * C2 * HWO + pS;

    float acc[16];
#pragma unroll
    for (int i = 0; i < 16; i++) acc[i] = 0.f;

    for (int t = 0; t < 9; t++) {
        int ti = t / 3, tj = t % 3;
        for (int dg = 0; dg < 2; dg++) {
            __syncthreads();   // previous GEMM done reading wts & vs

            // stage weights for (t, dg): 2304 floats = 576 float4
            {
                const float4* gw = (const float4*)(g_wt + (t * C1 + dg * 64) * C2);
                float4* wd = (float4*)wts;
                wd[tid] = gw[tid];                       // tid < 288
                if (tid < 288) wd[tid + 288] = gw[tid + 288];
            }

            // sampling (threads 0..255): V[sc0..sc0+31][sp]
            if (tid < 256) {
                float dy = offbase[(dg * 18 + t * 2    ) * HWO];
                float dx = offbase[(dg * 18 + t * 2 + 1) * HWO];
                float py = (float)(ysS + ti) + dy;
                float px = (float)(xsS + tj) + dx;
                float fy0 = floorf(py), fx0 = floorf(px);
                float wy1 = py - fy0, wx1 = px - fx0;
                float wy0 = 1.f - wy1, wx0 = 1.f - wx1;
                bool vy0 = (fy0       >= 0.f) && (fy0       <= (float)(Hh - 1));
                bool vy1 = (fy0 + 1.f >= 0.f) && (fy0 + 1.f <= (float)(Hh - 1));
                bool vx0 = (fx0       >= 0.f) && (fx0       <= (float)(Ww - 1));
                bool vx1 = (fx0 + 1.f >= 0.f) && (fx0 + 1.f <= (float)(Ww - 1));
                int y0i = (int)fy0, x0i = (int)fx0;
                int y0c = min(max(y0i,     0), Hh - 1);
                int y1c = min(max(y0i + 1, 0), Hh - 1);
                int x0c = min(max(x0i,     0), Ww - 1);
                int x1c = min(max(x0i + 1, 0), Ww - 1);
                float W00 = wy0 * wx0 * ((vy0 && vx0) ? 1.f : 0.f);
                float W01 = wy0 * wx1 * ((vy0 && vx1) ? 1.f : 0.f);
                float W10 = wy1 * wx0 * ((vy1 && vx0) ? 1.f : 0.f);
                float W11 = wy1 * wx1 * ((vy1 && vx1) ? 1.f : 0.f);
                int o00 = y0c * Ww + x0c, o01 = y0c * Ww + x1c;
                int o10 = y1c * Ww + x0c, o11 = y1c * Ww + x1c;

                const float* pc = xb + (dg * 64 + sc0) * HW;
                float* vrow = vs + sc0 * PB + sp;
#pragma unroll 4
                for (int c = 0; c < 32; c++) {
                    const float* pp = pc + c * HW;
                    float v = fmaf(W00, __ldg(pp + o00),
                              fmaf(W01, __ldg(pp + o01),
                              fmaf(W10, __ldg(pp + o10),
                                   W11 * __ldg(pp + o11))));
                    vrow[c * PB] = v;
                }
            }
            __syncthreads();   // wts + vs ready

            // GEMM: acc[4o][4p] += W[c][to*4..+3] * V[c][tp*4..+3]
            const float4* w4 = (const float4*)wts;
            const float4* v4 = (const float4*)vs;
#pragma unroll 16
            for (int c = 0; c < 64; c++) {
                float4 wv = w4[c * 9 + to];
                float4 vv = v4[c * 32 + tp];
                acc[0]  = fmaf(wv.x, vv.x, acc[0]);
                acc[1]  = fmaf(wv.x, vv.y, acc[1]);
                acc[2]  = fmaf(wv.x, vv.z, acc[2]);
                acc[3]  = fmaf(wv.x, vv.w, acc[3]);
                acc[4]  = fmaf(wv.y, vv.x, acc[4]);
                acc[5]  = fmaf(wv.y, vv.y, acc[5]);
                acc[6]  = fmaf(wv.y, vv.z, acc[6]);
                acc[7]  = fmaf(wv.y, vv.w, acc[7]);
                acc[8]  = fmaf(wv.z, vv.x, acc[8]);
                acc[9]  = fmaf(wv.z, vv.y, acc[9]);
                acc[10] = fmaf(wv.z, vv.z, acc[10]);
                acc[11] = fmaf(wv.z, vv.w, acc[11]);
                acc[12] = fmaf(wv.w, vv.x, acc[12]);
                acc[13] = fmaf(wv.w, vv.y, acc[13]);
                acc[14] = fmaf(wv.w, vv.z, acc[14]);
                acc[15] = fmaf(wv.w, vv.w, acc[15]);
            }
        }
    }

    // epilogue: bias + Mish, strided stores
#pragma unroll
    for (int i = 0; i < 4; i++) {
        int o = to * 4 + i;
        float b = __ldg(g_bias + o);
        float* ob = out + (size_t)n * C2 * HWO + (size_t)o * HWO;
#pragma unroll
        for (int j = 0; j < 4; j++) {
            int p = p0 + tp * 4 + j;
            if (p < HWO) {
                float z = acc[i * 4 + j] + b;
                float spv = (z > 20.f) ? z : log1pf(expf(z));
                ob[p] = z * tanhf(spv);
            }
        }
    }
}

// ---------------------------------------------------------------------------
extern "C" void kernel_launch(void* const* d_in, const int* in_sizes, int n_in,
                              void* d_out, int out_size)
{
    const float* x        = (const float*)d_in[0];
    const float* conv_w   = (const float*)d_in[1];
    const float* deform_w = (const float*)d_in[2];
    const float* bn_gamma = (const float*)d_in[3];
    const float* bn_beta  = (const float*)d_in[4];
    const float* bn_mean  = (const float*)d_in[5];
    const float* bn_var   = (const float*)d_in[6];
    float* out = (float*)d_out;

    prep_kernel<<<(9 * C1 * C2 + 255) / 256, 256>>>(
        deform_w, bn_gamma, bn_beta, bn_mean, bn_var);

    // offset conv: 32x6 output tiles -> grid (6, 32, 16)
    offset_conv_kernel<<<dim3(6, 32, 16), 192>>>(x, conv_w);

    // deform conv: 128 pixels per block
    deform_kernel<<<dim3((HWO + PB - 1) / PB, NN), NT>>>(x, out);
}